// round 2
// baseline (speedup 1.0000x reference)
#include <cuda_runtime.h>
#include <cuda_bf16.h>

#define NBINS 256
#define NIMG  96
#define HDIM  512
#define WDIM  512
#define CHUNK 16
#define PI_F  3.14159265358979323846f

// scratch for per-image max (allocation-free per harness rules)
__device__ float g_vmax[NIMG];

// ---------------------------------------------------------------------------
// Kernel 1: soft co-occurrence histogram scatter.
// Each thread owns one column and CHUNK consecutive vertical pairs, carrying
// the previous pixel's (bin, weight) in registers so each pixel's
// floor/cos is computed exactly once.
// ---------------------------------------------------------------------------
__global__ void __launch_bounds__(256) hist_kernel(const float* __restrict__ X,
                                                   float* __restrict__ hist) {
    const int img = blockIdx.z;
    const int col = blockIdx.x * blockDim.x + threadIdx.x;
    const int r0  = blockIdx.y * CHUNK;
    if (col >= WDIM) return;

    const float* __restrict__ base = X + (size_t)img * (HDIM * WDIM) + col;
    float* __restrict__ h = hist + (size_t)img * (NBINS * NBINS);

    // first pixel of the chunk (the 'a' of the first pair)
    float a  = __ldg(base + (size_t)r0 * WDIM);
    float fa = fminf(floorf(a), 254.0f);         // clamp for memory safety
    int   ia = (int)fa;
    float wa0 = 0.5f * (1.0f + __cosf(PI_F * (a - fa)));

    const int rmax = min(r0 + CHUNK, HDIM - 1);
    for (int r = r0; r < rmax; ++r) {
        float b  = __ldg(base + (size_t)(r + 1) * WDIM);
        float fb = fminf(floorf(b), 254.0f);
        int   ib = (int)fb;
        float wb0 = 0.5f * (1.0f + __cosf(PI_F * (b - fb)));

        float wa1 = 1.0f - wa0;
        float wb1 = 1.0f - wb0;

        float* row0 = h + ia * NBINS + ib;
        float* row1 = row0 + NBINS;              // ia+1 row, same ib
        atomicAdd(row0,     wa0 * wb0);
        atomicAdd(row0 + 1, wa0 * wb1);
        atomicAdd(row1,     wa1 * wb0);
        atomicAdd(row1 + 1, wa1 * wb1);

        // carry b forward as next pair's a
        a = b; ia = ib; wa0 = wb0;
    }
}

// ---------------------------------------------------------------------------
// Kernel 2: per-image max over the 256x256 histogram.
// One block per image, float4 strided loads + warp/smem tree reduce.
// ---------------------------------------------------------------------------
__global__ void __launch_bounds__(512) max_kernel(const float* __restrict__ hist) {
    const int img = blockIdx.x;
    const float4* __restrict__ h4 =
        reinterpret_cast<const float4*>(hist + (size_t)img * (NBINS * NBINS));
    const int n4 = (NBINS * NBINS) / 4;   // 16384

    float m = 0.0f;                        // hist values are >= 0
    for (int i = threadIdx.x; i < n4; i += blockDim.x) {
        float4 v = h4[i];
        m = fmaxf(m, fmaxf(fmaxf(v.x, v.y), fmaxf(v.z, v.w)));
    }
    #pragma unroll
    for (int o = 16; o > 0; o >>= 1)
        m = fmaxf(m, __shfl_xor_sync(0xFFFFFFFFu, m, o));

    __shared__ float sm[16];
    if ((threadIdx.x & 31) == 0) sm[threadIdx.x >> 5] = m;
    __syncthreads();
    if (threadIdx.x < 32) {
        m = (threadIdx.x < (blockDim.x >> 5)) ? sm[threadIdx.x] : 0.0f;
        #pragma unroll
        for (int o = 16; o > 0; o >>= 1)
            m = fmaxf(m, __shfl_xor_sync(0xFFFFFFFFu, m, o));
        if (threadIdx.x == 0) g_vmax[img] = m;
    }
}

// ---------------------------------------------------------------------------
// Kernel 3: scale each histogram by 1/vmax (float4 vectorized).
// ---------------------------------------------------------------------------
__global__ void __launch_bounds__(256) norm_kernel(float* __restrict__ hist) {
    const int img = blockIdx.y;
    const float vmax = g_vmax[img];
    float4* __restrict__ h4 =
        reinterpret_cast<float4*>(hist + (size_t)img * (NBINS * NBINS));
    const int i = blockIdx.x * blockDim.x + threadIdx.x;   // [0, 16384)
    float4 v = h4[i];
    v.x /= vmax; v.y /= vmax; v.z /= vmax; v.w /= vmax;
    h4[i] = v;
}

// ---------------------------------------------------------------------------
extern "C" void kernel_launch(void* const* d_in, const int* in_sizes, int n_in,
                              void* d_out, int out_size) {
    const float* X = (const float*)d_in[0];
    float* out = (float*)d_out;

    // d_out is poisoned; we accumulate into it, so zero first.
    cudaMemsetAsync(out, 0, (size_t)NIMG * NBINS * NBINS * sizeof(float), 0);

    // scatter: x = column halves, y = row chunks, z = images
    dim3 grid(WDIM / 256, (HDIM - 1 + CHUNK - 1) / CHUNK, NIMG);
    hist_kernel<<<grid, 256>>>(X, out);

    max_kernel<<<NIMG, 512>>>(out);

    dim3 ngrid((NBINS * NBINS / 4) / 256, NIMG);
    norm_kernel<<<ngrid, 256>>>(out);
}

// round 3
// speedup vs baseline: 1.5390x; 1.5390x over previous
#include <cuda_runtime.h>
#include <cuda_bf16.h>

#define NBINS 256
#define NIMG  96
#define HDIM  512
#define WDIM  512
#define CHUNK 16
#define PI_F  3.14159265358979323846f

// scratch for per-image max (allocation-free per harness rules)
__device__ float g_vmax[NIMG];

// ---------------------------------------------------------------------------
// Vectorized / scalar global float reductions (sm_90+ for v4)
// ---------------------------------------------------------------------------
__device__ __forceinline__ void red4(float* a, float x, float y, float z, float w) {
    asm volatile("red.global.add.v4.f32 [%0], {%1,%2,%3,%4};"
                 :: "l"(a), "f"(x), "f"(y), "f"(z), "f"(w) : "memory");
}
__device__ __forceinline__ void red1(float* a, float x) {
    asm volatile("red.global.add.f32 [%0], %1;"
                 :: "l"(a), "f"(x) : "memory");
}

// ---------------------------------------------------------------------------
// Kernel 1: soft co-occurrence histogram scatter.
// Each thread owns one column and CHUNK consecutive vertical pairs, carrying
// the previous pixel's (bin, weight) in registers. The 2x2 raised-cosine
// stamp is emitted as two v4 reductions when (ib % 4) != 3 (16B window
// covers both columns), scalar reds otherwise.
// ---------------------------------------------------------------------------
__global__ void __launch_bounds__(256) hist_kernel(const float* __restrict__ X,
                                                   float* __restrict__ hist) {
    const int img = blockIdx.z;
    const int col = blockIdx.x * blockDim.x + threadIdx.x;
    const int r0  = blockIdx.y * CHUNK;
    if (col >= WDIM) return;

    const float* __restrict__ base = X + (size_t)img * (HDIM * WDIM) + col;
    float* __restrict__ h = hist + (size_t)img * (NBINS * NBINS);

    // first pixel of the chunk (the 'a' of the first pair)
    float a  = __ldg(base + (size_t)r0 * WDIM);
    float fa = fminf(floorf(a), 254.0f);          // exact-equivalent clamp
    int   ia = (int)fa;
    float wa0 = 0.5f * (1.0f + __cosf(PI_F * (a - fa)));

    const int rmax = min(r0 + CHUNK, HDIM - 1);
    for (int r = r0; r < rmax; ++r) {
        float b  = __ldg(base + (size_t)(r + 1) * WDIM);
        float fb = fminf(floorf(b), 254.0f);
        int   ib = (int)fb;
        float wb0 = 0.5f * (1.0f + __cosf(PI_F * (b - fb)));

        float wa1 = 1.0f - wa0;
        float wb1 = 1.0f - wb0;

        const int j = ib & 3;
        float* base0 = h + ia * NBINS + (ib & ~3);   // 16B-aligned window
        float* base1 = base0 + NBINS;                // ia+1 row

        if (j != 3) {
            // place (wb0, wb1) at lanes j, j+1 of the v4 word
            float e0 = (j == 0) ? wb0 : 0.0f;
            float e1 = (j == 0) ? wb1 : ((j == 1) ? wb0 : 0.0f);
            float e2 = (j == 1) ? wb1 : ((j == 2) ? wb0 : 0.0f);
            float e3 = (j == 2) ? wb1 : 0.0f;
            red4(base0, wa0 * e0, wa0 * e1, wa0 * e2, wa0 * e3);
            red4(base1, wa1 * e0, wa1 * e1, wa1 * e2, wa1 * e3);
        } else {
            // columns ib=.3 and ib+1=.0 straddle the 16B boundary
            red1(base0 + 3, wa0 * wb0);
            red1(base0 + 4, wa0 * wb1);
            red1(base1 + 3, wa1 * wb0);
            red1(base1 + 4, wa1 * wb1);
        }

        // carry b forward as next pair's a
        a = b; ia = ib; wa0 = wb0;
    }
}

// ---------------------------------------------------------------------------
// Kernel 2: per-image max over the 256x256 histogram.
// ---------------------------------------------------------------------------
__global__ void __launch_bounds__(512) max_kernel(const float* __restrict__ hist) {
    const int img = blockIdx.x;
    const float4* __restrict__ h4 =
        reinterpret_cast<const float4*>(hist + (size_t)img * (NBINS * NBINS));
    const int n4 = (NBINS * NBINS) / 4;   // 16384

    float m = 0.0f;                        // hist values are >= 0
    for (int i = threadIdx.x; i < n4; i += blockDim.x) {
        float4 v = h4[i];
        m = fmaxf(m, fmaxf(fmaxf(v.x, v.y), fmaxf(v.z, v.w)));
    }
    #pragma unroll
    for (int o = 16; o > 0; o >>= 1)
        m = fmaxf(m, __shfl_xor_sync(0xFFFFFFFFu, m, o));

    __shared__ float sm[16];
    if ((threadIdx.x & 31) == 0) sm[threadIdx.x >> 5] = m;
    __syncthreads();
    if (threadIdx.x < 32) {
        m = (threadIdx.x < (blockDim.x >> 5)) ? sm[threadIdx.x] : 0.0f;
        #pragma unroll
        for (int o = 16; o > 0; o >>= 1)
            m = fmaxf(m, __shfl_xor_sync(0xFFFFFFFFu, m, o));
        if (threadIdx.x == 0) g_vmax[img] = m;
    }
}

// ---------------------------------------------------------------------------
// Kernel 3: scale each histogram by 1/vmax (float4 vectorized).
// ---------------------------------------------------------------------------
__global__ void __launch_bounds__(256) norm_kernel(float* __restrict__ hist) {
    const int img = blockIdx.y;
    const float vmax = g_vmax[img];
    float4* __restrict__ h4 =
        reinterpret_cast<float4*>(hist + (size_t)img * (NBINS * NBINS));
    const int i = blockIdx.x * blockDim.x + threadIdx.x;   // [0, 16384)
    float4 v = h4[i];
    v.x /= vmax; v.y /= vmax; v.z /= vmax; v.w /= vmax;
    h4[i] = v;
}

// ---------------------------------------------------------------------------
extern "C" void kernel_launch(void* const* d_in, const int* in_sizes, int n_in,
                              void* d_out, int out_size) {
    const float* X = (const float*)d_in[0];
    float* out = (float*)d_out;

    // d_out is poisoned; we accumulate into it, so zero first.
    cudaMemsetAsync(out, 0, (size_t)NIMG * NBINS * NBINS * sizeof(float), 0);

    // scatter: x = column halves, y = row chunks, z = images
    dim3 grid(WDIM / 256, (HDIM - 1 + CHUNK - 1) / CHUNK, NIMG);
    hist_kernel<<<grid, 256>>>(X, out);

    max_kernel<<<NIMG, 512>>>(out);

    dim3 ngrid((NBINS * NBINS / 4) / 256, NIMG);
    norm_kernel<<<ngrid, 256>>>(out);
}

// round 4
// speedup vs baseline: 2.4776x; 1.6099x over previous
#include <cuda_runtime.h>
#include <cuda_bf16.h>

#define NBINS 256
#define NIMG  96
#define BATCH 24            // images per batch (4 batches)
#define HDIM  512
#define WDIM  512
#define CHUNK 16
#define PI_F  3.14159265358979323846f

// 4 parity copies x BATCH images x 128x128 tiles x 4 floats = 25.2 MB scratch
#define TILES_PER_IMG (128 * 128)
#define SCRATCH_F4    (4 * BATCH * TILES_PER_IMG)
__device__ float4 g_scratch[SCRATCH_F4];
__device__ float  g_vmax[NIMG];

__device__ __forceinline__ void red4(float* a, float x, float y, float z, float w) {
    asm volatile("red.global.add.v4.f32 [%0], {%1,%2,%3,%4};"
                 :: "l"(a), "f"(x), "f"(y), "f"(z), "f"(w) : "memory");
}

// ---------------------------------------------------------------------------
// Zero the scratch (graph-capturable, no memset API needed)
// ---------------------------------------------------------------------------
__global__ void __launch_bounds__(256) zero_kernel() {
    const int i = blockIdx.x * blockDim.x + threadIdx.x;
    g_scratch[i] = make_float4(0.f, 0.f, 0.f, 0.f);
}

// ---------------------------------------------------------------------------
// Kernel 1: soft co-occurrence scatter, ONE v4 red per pair.
// Parity copy c = (ia&1)*2 + (ib&1); tile (tr,tc) = ((ia+1)>>1, (ib+1)>>1).
// Tile lane layout: {row ia col ib, row ia col ib+1, row ia+1 col ib, row ia+1 col ib+1}.
// ---------------------------------------------------------------------------
__global__ void __launch_bounds__(256) hist_kernel(const float* __restrict__ X,
                                                   int img0) {
    const int img_l = blockIdx.z;                    // local image in batch
    const int col   = blockIdx.x * blockDim.x + threadIdx.x;
    const int r0    = blockIdx.y * CHUNK;

    const float* __restrict__ base =
        X + (size_t)(img0 + img_l) * (HDIM * WDIM) + col;
    float* __restrict__ sc = reinterpret_cast<float*>(g_scratch);

    float a  = __ldg(base + (size_t)r0 * WDIM);
    float fa = fminf(floorf(a), 254.0f);
    int   ia = (int)fa;
    float wa0 = 0.5f * (1.0f + __cosf(PI_F * (a - fa)));

    const int rmax = min(r0 + CHUNK, HDIM - 1);
    for (int r = r0; r < rmax; ++r) {
        float b  = __ldg(base + (size_t)(r + 1) * WDIM);
        float fb = fminf(floorf(b), 254.0f);
        int   ib = (int)fb;
        float wb0 = 0.5f * (1.0f + __cosf(PI_F * (b - fb)));

        const float wa1 = 1.0f - wa0;
        const float wb1 = 1.0f - wb0;

        const int c  = ((ia & 1) << 1) | (ib & 1);
        const int tr = (ia + 1) >> 1;
        const int tc = (ib + 1) >> 1;
        float* p = sc + ((((c * BATCH + img_l) << 14) + (tr << 7) + tc) << 2);
        red4(p, wa0 * wb0, wa0 * wb1, wa1 * wb0, wa1 * wb1);

        a = b; ia = ib; wa0 = wb0;                   // carry pixel forward
    }
}

// ---------------------------------------------------------------------------
// Kernel 2: merge the 4 parity copies into the output histogram.
// out[i][j] = sum over (pr,pc) of copy value at tile ((i+pr)>>1,(j+pc)>>1),
// lane ((i+pr)&1)*2 + ((j+pc)&1). Tile index 128 (i=255,p=1) was never
// written -> guarded to 0.
// ---------------------------------------------------------------------------
__global__ void __launch_bounds__(256) merge_kernel(float* __restrict__ out,
                                                    int img0) {
    const int img_l = blockIdx.y;
    const int idx = blockIdx.x * blockDim.x + threadIdx.x;   // [0, 65536)
    const int i = idx >> 8;
    const int j = idx & 255;
    const float* __restrict__ sc = reinterpret_cast<const float*>(g_scratch);

    float s = 0.0f;
    #pragma unroll
    for (int pr = 0; pr < 2; ++pr) {
        #pragma unroll
        for (int pc = 0; pc < 2; ++pc) {
            const int tr = (i + pr) >> 1;
            const int tc = (j + pc) >> 1;
            if (tr < 128 && tc < 128) {
                const int c    = (pr << 1) | pc;
                const int lane = (((i + pr) & 1) << 1) | ((j + pc) & 1);
                s += sc[((((c * BATCH + img_l) << 14) + (tr << 7) + tc) << 2) + lane];
            }
        }
    }
    out[((size_t)(img0 + img_l) << 16) + idx] = s;
}

// ---------------------------------------------------------------------------
// Kernel 3: per-image max over the 256x256 histogram.
// ---------------------------------------------------------------------------
__global__ void __launch_bounds__(512) max_kernel(const float* __restrict__ hist) {
    const int img = blockIdx.x;
    const float4* __restrict__ h4 =
        reinterpret_cast<const float4*>(hist + ((size_t)img << 16));
    const int n4 = (NBINS * NBINS) / 4;

    float m = 0.0f;
    for (int i = threadIdx.x; i < n4; i += blockDim.x) {
        float4 v = h4[i];
        m = fmaxf(m, fmaxf(fmaxf(v.x, v.y), fmaxf(v.z, v.w)));
    }
    #pragma unroll
    for (int o = 16; o > 0; o >>= 1)
        m = fmaxf(m, __shfl_xor_sync(0xFFFFFFFFu, m, o));

    __shared__ float sm[16];
    if ((threadIdx.x & 31) == 0) sm[threadIdx.x >> 5] = m;
    __syncthreads();
    if (threadIdx.x < 32) {
        m = (threadIdx.x < (blockDim.x >> 5)) ? sm[threadIdx.x] : 0.0f;
        #pragma unroll
        for (int o = 16; o > 0; o >>= 1)
            m = fmaxf(m, __shfl_xor_sync(0xFFFFFFFFu, m, o));
        if (threadIdx.x == 0) g_vmax[img] = m;
    }
}

// ---------------------------------------------------------------------------
// Kernel 4: scale each histogram by 1/vmax.
// ---------------------------------------------------------------------------
__global__ void __launch_bounds__(256) norm_kernel(float* __restrict__ hist) {
    const int img = blockIdx.y;
    const float vmax = g_vmax[img];
    float4* __restrict__ h4 = reinterpret_cast<float4*>(hist + ((size_t)img << 16));
    const int i = blockIdx.x * blockDim.x + threadIdx.x;
    float4 v = h4[i];
    v.x /= vmax; v.y /= vmax; v.z /= vmax; v.w /= vmax;
    h4[i] = v;
}

// ---------------------------------------------------------------------------
extern "C" void kernel_launch(void* const* d_in, const int* in_sizes, int n_in,
                              void* d_out, int out_size) {
    const float* X = (const float*)d_in[0];
    float* out = (float*)d_out;

    const dim3 hgrid(WDIM / 256, (HDIM - 1 + CHUNK - 1) / CHUNK, BATCH);
    const dim3 mgrid(65536 / 256, BATCH);

    for (int b = 0; b < NIMG / BATCH; ++b) {
        zero_kernel<<<SCRATCH_F4 / 256, 256>>>();
        hist_kernel<<<hgrid, 256>>>(X, b * BATCH);
        merge_kernel<<<mgrid, 256>>>(out, b * BATCH);
    }

    max_kernel<<<NIMG, 512>>>(out);
    dim3 ngrid((NBINS * NBINS / 4) / 256, NIMG);
    norm_kernel<<<ngrid, 256>>>(out);
}